// round 2
// baseline (speedup 1.0000x reference)
#include <cuda_runtime.h>
#include <cstdint>

#define D      128
#define MAXN   100000
#define GROWS  16   // rows per GEMM block

// Scratch (allocation-free contract: __device__ globals)
__device__ float g_deg[MAXN];
__device__ float g_dinv[MAXN];
__device__ float g_h[(size_t)MAXN * D];
__device__ int   g_is64;

// ---------------------------------------------------------------------------
// Kernel 0: detect edge_index storage dtype (int32 vs int64).
// int64 little-endian => every odd int32 word (hi half of a value < 2^31) is 0.
// int32 => odd words are genuine indices; among 1024 random values in
// [0,100000) at least one is nonzero with probability ~1.
// ---------------------------------------------------------------------------
__global__ void detect_dtype_kernel(const int* __restrict__ ei32, int n_i32) {
    __shared__ int any_nonzero;
    if (threadIdx.x == 0) any_nonzero = 0;
    __syncthreads();
    int n = min(1024, n_i32 / 2);
    for (int i = threadIdx.x; i < n; i += blockDim.x)
        if (ei32[2 * i + 1] != 0) any_nonzero = 1;
    __syncthreads();
    if (threadIdx.x == 0) g_is64 = (any_nonzero == 0) ? 1 : 0;
}

__device__ __forceinline__ long long load_idx(const void* ei, int is64, size_t pos) {
    if (is64) return ((const long long*)ei)[pos];
    return (long long)((const int*)ei)[pos];
}

// ---------------------------------------------------------------------------
// Kernel 1: deg[i] = 1.0 (self-loop weight, renorm trick)
// ---------------------------------------------------------------------------
__global__ void init_deg_kernel(int N) {
    int i = blockIdx.x * blockDim.x + threadIdx.x;
    if (i < N) g_deg[i] = 1.0f;
}

// ---------------------------------------------------------------------------
// Kernel 2: deg[row[e]] += w[e]
// ---------------------------------------------------------------------------
__global__ void accum_deg_kernel(const void* __restrict__ ei,
                                 const float* __restrict__ ew, int E) {
    int i = blockIdx.x * blockDim.x + threadIdx.x;
    if (i < E) {
        long long r = load_idx(ei, g_is64, i);  // row = edge_index[0]
        atomicAdd(&g_deg[r], ew[i]);
    }
}

// ---------------------------------------------------------------------------
// Kernel 3: h = x @ W ; dinv = rsqrt(deg) ; out = dinv^2 * h + bias
// 128 threads/block (one per output column), GROWS rows per block.
// W rows are read coalesced and stay L1-resident (64 KB < 228 KB L1).
// ---------------------------------------------------------------------------
__global__ void __launch_bounds__(D)
gemm_selfloop_kernel(const float* __restrict__ x,
                     const float* __restrict__ W,
                     const float* __restrict__ bias,
                     float* __restrict__ out, int N) {
    __shared__ float xs[GROWS][D];
    const int t  = threadIdx.x;          // output column
    const int r0 = blockIdx.x * GROWS;

    #pragma unroll
    for (int j = 0; j < GROWS; j++) {
        int r = r0 + j;
        xs[j][t] = (r < N) ? x[(size_t)r * D + t] : 0.0f;
    }
    __syncthreads();

    float acc[GROWS];
    #pragma unroll
    for (int j = 0; j < GROWS; j++) acc[j] = 0.0f;

    #pragma unroll 4
    for (int k = 0; k < D; k++) {
        float w = W[k * D + t];          // coalesced, L1-hot
        #pragma unroll
        for (int j = 0; j < GROWS; j++)
            acc[j] += xs[j][k] * w;      // xs broadcast: conflict-free
    }

    const float b = bias[t];
    #pragma unroll
    for (int j = 0; j < GROWS; j++) {
        int r = r0 + j;
        if (r < N) {
            float dg = g_deg[r];
            float dv = (dg > 0.0f) ? rsqrtf(dg) : 0.0f;
            if (t == 0) g_dinv[r] = dv;
            float h = acc[j];
            g_h[(size_t)r * D + t] = h;
            out[(size_t)r * D + t] = dv * dv * h + b;   // self-loop + bias
        }
    }
}

// ---------------------------------------------------------------------------
// Kernel 4: edge scatter. One warp per edge; each lane handles 4 columns.
// Gather h[col] (L2-resident), reduce into out[row] via red.global.add.v4.f32
// (4x fewer RED issue slots than scalar atomicAdd).
// ---------------------------------------------------------------------------
__global__ void __launch_bounds__(256)
scatter_kernel(const void* __restrict__ ei,
               const float* __restrict__ ew,
               float* __restrict__ out, int E) {
    int gt   = blockIdx.x * blockDim.x + threadIdx.x;
    int e    = gt >> 5;
    int lane = gt & 31;
    if (e >= E) return;

    const int is64 = g_is64;
    long long r = load_idx(ei, is64, e);                 // row
    long long c = load_idx(ei, is64, (size_t)E + e);     // col
    float w = ew[e] * g_dinv[r] * g_dinv[c];

    float4 v = reinterpret_cast<const float4*>(g_h + (size_t)c * D)[lane];
    float* o = out + (size_t)r * D + (lane << 2);
    asm volatile("red.global.add.v4.f32 [%0], {%1,%2,%3,%4};"
                 :: "l"(o), "f"(w * v.x), "f"(w * v.y),
                    "f"(w * v.z), "f"(w * v.w)
                 : "memory");
}

// ---------------------------------------------------------------------------
extern "C" void kernel_launch(void* const* d_in, const int* in_sizes, int n_in,
                              void* d_out, int out_size) {
    const float* x    = (const float*)d_in[0];    // [N, 128]
    const void*  ei   = d_in[1];                  // [2, E] int64-or-int32
    const float* ew   = (const float*)d_in[2];    // [E]
    const float* W    = (const float*)d_in[3];    // [128, 128]
    const float* bias = (const float*)d_in[4];    // [128]
    float*       out  = (float*)d_out;            // [N, 128]

    const int N = in_sizes[0] / D;
    const int E = in_sizes[2];

    // 0) detect int32 vs int64 edge_index storage.
    // If the harness reports int64 element counts, in_sizes[1] == 2*E either
    // way, so detect from the data itself. n_i32: safe lower bound = 2*E.
    detect_dtype_kernel<<<1, 256>>>((const int*)ei, 2 * E);

    // 1) deg = 1 (self loops)
    init_deg_kernel<<<(N + 255) / 256, 256>>>(N);

    // 2) deg[row] += w
    accum_deg_kernel<<<(E + 255) / 256, 256>>>(ei, ew, E);

    // 3) h = xW, dinv, out = dinv^2*h + bias
    gemm_selfloop_kernel<<<(N + GROWS - 1) / GROWS, D>>>(x, W, bias, out, N);

    // 4) out[row] += norm_w * h[col]   (one warp per edge)
    long long total_threads = (long long)E * 32;
    int blocks = (int)((total_threads + 255) / 256);
    scatter_kernel<<<blocks, 256>>>(ei, ew, out, E);
}